// round 1
// baseline (speedup 1.0000x reference)
#include <cuda_runtime.h>

#define N_NODES 100000
#define E_EDGES 400000
#define DN 64
#define DE 32
#define DH 64
#define DIN_E 160
#define DIN_N 128
#define TE 64
#define TN 64
#define NT 256

#define SIN_E_STRIDE 164   // 160 + 4 pad (16B-aligned rows, bank-skewed)
#define SIN_N_STRIDE 132   // 128 + 4 pad
#define SH_STRIDE 68       // 64 + 4 pad

// Scratch for segment sums/counts (no cudaMalloc allowed).
// slots: 0 = a<-aa(row), 1 = a<-ab(row), 2 = b<-ab(col), 3 = b<-bb(row)
__device__ float g_sum[4][N_NODES * DE];
__device__ float g_cnt[4][N_NODES];

__global__ void zero_kernel() {
    int idx = blockIdx.x * blockDim.x + threadIdx.x;
    int stride = gridDim.x * blockDim.x;
    float* s = &g_sum[0][0];
    for (int i = idx; i < 4 * N_NODES * DE; i += stride) s[i] = 0.0f;
    float* c = &g_cnt[0][0];
    for (int i = idx; i < 4 * N_NODES; i += stride) c[i] = 0.0f;
}

// ---------------------------------------------------------------------------
// Edge kernel: per block, 64 edges. Gather [src|dst|ea] (160), 2-layer MLP,
// write ne, atomically scatter into segment sums.
// Layer1: 256 thr as 16(te) x 16(th); each thread computes 4 edges x 4 hidden.
// Layer2: each thread computes 4 edges x 2 outputs.
// ---------------------------------------------------------------------------
__global__ void __launch_bounds__(NT) edge_kernel(
    const float* __restrict__ xsrc, const float* __restrict__ xdst,
    const int* __restrict__ ei, const float* __restrict__ ea,
    const float* __restrict__ W1, const float* __restrict__ b1,
    const float* __restrict__ W2, const float* __restrict__ b2,
    float* __restrict__ ne_out, int slot_row, int slot_col)
{
    extern __shared__ float sm[];
    float* sW1 = sm;                         // 160*64
    float* sW2 = sW1 + DIN_E * DH;           // 64*32
    float* sb1 = sW2 + DH * DE;              // 64
    float* sb2 = sb1 + DH;                   // 32
    float* sIn = sb2 + DE;                   // 64 * 164
    float* sH  = sIn + TE * SIN_E_STRIDE;    // 64 * 68
    int* sIdxR = (int*)(sH + TE * SH_STRIDE);
    int* sIdxC = sIdxR + TE;

    const int tid = threadIdx.x;
    const int e0 = blockIdx.x * TE;

    // Stage weights/biases in shared
    for (int i = tid; i < DIN_E * DH / 4; i += NT)
        ((float4*)sW1)[i] = ((const float4*)W1)[i];
    for (int i = tid; i < DH * DE / 4; i += NT)
        ((float4*)sW2)[i] = ((const float4*)W2)[i];
    if (tid < DH) sb1[tid] = b1[tid];
    else if (tid < DH + DE) sb2[tid - DH] = b2[tid - DH];
    if (tid < TE) {
        int ge = e0 + tid; if (ge >= E_EDGES) ge = E_EDGES - 1;
        sIdxR[tid] = ei[ge];
        sIdxC[tid] = ei[E_EDGES + ge];
    }
    __syncthreads();

    // Gather inputs: 40 float4 chunks per edge, e-major so global reads
    // stream contiguously along each gathered row.
    for (int item = tid; item < TE * 40; item += NT) {
        int e = item / 40;
        int c4 = item - e * 40;
        int ge = e0 + e;
        float4 v = make_float4(0.f, 0.f, 0.f, 0.f);
        if (ge < E_EDGES) {
            if (c4 < 16)      v = ((const float4*)(xsrc + sIdxR[e] * DN))[c4];
            else if (c4 < 32) v = ((const float4*)(xdst + sIdxC[e] * DN))[c4 - 16];
            else              v = ((const float4*)(ea + ge * DE))[c4 - 32];
        }
        *(float4*)(sIn + e * SIN_E_STRIDE + c4 * 4) = v;
    }
    __syncthreads();

    const int th = tid & 15;
    const int te = tid >> 4;

    // ---- Layer 1: [64e x 160] @ [160 x 64h] ----
    float acc[4][4];
    {
        const float4 b = *(const float4*)(sb1 + th * 4);
        #pragma unroll
        for (int i = 0; i < 4; i++) {
            acc[i][0] = b.x; acc[i][1] = b.y; acc[i][2] = b.z; acc[i][3] = b.w;
        }
    }
    const float* inRow = sIn + (te * 4) * SIN_E_STRIDE;
    for (int k = 0; k < DIN_E; k += 4) {
        float4 av4[4];
        #pragma unroll
        for (int i = 0; i < 4; i++)
            av4[i] = *(const float4*)(inRow + i * SIN_E_STRIDE + k);
        const float* a = (const float*)av4;
        #pragma unroll
        for (int kk = 0; kk < 4; kk++) {
            float4 w = *(const float4*)(sW1 + (k + kk) * DH + th * 4);
            #pragma unroll
            for (int i = 0; i < 4; i++) {
                float x = a[i * 4 + kk];
                acc[i][0] += x * w.x;
                acc[i][1] += x * w.y;
                acc[i][2] += x * w.z;
                acc[i][3] += x * w.w;
            }
        }
    }
    // ReLU -> sH (e-major)
    #pragma unroll
    for (int i = 0; i < 4; i++) {
        float4 h;
        h.x = fmaxf(acc[i][0], 0.f);
        h.y = fmaxf(acc[i][1], 0.f);
        h.z = fmaxf(acc[i][2], 0.f);
        h.w = fmaxf(acc[i][3], 0.f);
        *(float4*)(sH + (te * 4 + i) * SH_STRIDE + th * 4) = h;
    }
    __syncthreads();

    // ---- Layer 2: [64e x 64h] @ [64h x 32o] ----
    float acc2[4][2];
    {
        float w0 = sb2[th * 2], w1 = sb2[th * 2 + 1];
        #pragma unroll
        for (int i = 0; i < 4; i++) { acc2[i][0] = w0; acc2[i][1] = w1; }
    }
    const float* hRow = sH + (te * 4) * SH_STRIDE;
    for (int k = 0; k < DH; k += 4) {
        float4 av4[4];
        #pragma unroll
        for (int i = 0; i < 4; i++)
            av4[i] = *(const float4*)(hRow + i * SH_STRIDE + k);
        const float* a = (const float*)av4;
        #pragma unroll
        for (int kk = 0; kk < 4; kk++) {
            float2 w = *(const float2*)(sW2 + (k + kk) * DE + th * 2);
            #pragma unroll
            for (int i = 0; i < 4; i++) {
                float x = a[i * 4 + kk];
                acc2[i][0] += x * w.x;
                acc2[i][1] += x * w.y;
            }
        }
    }

    // ---- Write ne + scatter atomics ----
    float* sum_row = g_sum[slot_row];
    float* cnt_row = g_cnt[slot_row];
    float* sum_col = (slot_col >= 0) ? g_sum[slot_col] : nullptr;
    float* cnt_col = (slot_col >= 0) ? g_cnt[slot_col] : nullptr;
    #pragma unroll
    for (int i = 0; i < 4; i++) {
        int e = te * 4 + i;
        int ge = e0 + e;
        if (ge < E_EDGES) {
            float vx = acc2[i][0], vy = acc2[i][1];
            float2 v; v.x = vx; v.y = vy;
            *(float2*)(ne_out + ge * DE + th * 2) = v;
            int r = sIdxR[e];
            atomicAdd(sum_row + r * DE + th * 2, vx);
            atomicAdd(sum_row + r * DE + th * 2 + 1, vy);
            if (slot_col >= 0) {
                int c = sIdxC[e];
                atomicAdd(sum_col + c * DE + th * 2, vx);
                atomicAdd(sum_col + c * DE + th * 2 + 1, vy);
            }
            if (th == 0) {
                atomicAdd(cnt_row + r, 1.0f);
                if (slot_col >= 0) atomicAdd(cnt_col + sIdxC[e], 1.0f);
            }
        }
    }
}

// ---------------------------------------------------------------------------
// Node kernel: per block, 64 nodes. Input = [x(64) | mean1(32) | mean2(32)],
// 2-layer MLP 128 -> 64(relu) -> 64, write nx.
// ---------------------------------------------------------------------------
__global__ void __launch_bounds__(NT) node_kernel(
    const float* __restrict__ x, int slot1, int slot2,
    const float* __restrict__ W1, const float* __restrict__ b1,
    const float* __restrict__ W2, const float* __restrict__ b2,
    float* __restrict__ out)
{
    extern __shared__ float sm[];
    float* sW1 = sm;                         // 128*64
    float* sW2 = sW1 + DIN_N * DH;           // 64*64
    float* sb1 = sW2 + DH * DN;              // 64
    float* sb2 = sb1 + DH;                   // 64
    float* sIn = sb2 + DN;                   // 64 * 132
    float* sH  = sIn + TN * SIN_N_STRIDE;    // 64 * 68

    const int tid = threadIdx.x;
    const int n0 = blockIdx.x * TN;
    const float* sum1 = g_sum[slot1];
    const float* cnt1 = g_cnt[slot1];
    const float* sum2 = g_sum[slot2];
    const float* cnt2 = g_cnt[slot2];

    for (int i = tid; i < DIN_N * DH / 4; i += NT)
        ((float4*)sW1)[i] = ((const float4*)W1)[i];
    for (int i = tid; i < DH * DN / 4; i += NT)
        ((float4*)sW2)[i] = ((const float4*)W2)[i];
    if (tid < DH) sb1[tid] = b1[tid];
    else if (tid < DH + DN) sb2[tid - DH] = b2[tid - DH];
    __syncthreads();

    // Build inputs: 32 float4 chunks per node
    for (int item = tid; item < TN * 32; item += NT) {
        int n = item >> 5;
        int c4 = item & 31;
        int gn = n0 + n;
        float4 v = make_float4(0.f, 0.f, 0.f, 0.f);
        if (gn < N_NODES) {
            if (c4 < 16) {
                v = ((const float4*)(x + gn * DN))[c4];
            } else if (c4 < 24) {
                v = ((const float4*)(sum1 + gn * DE))[c4 - 16];
                float c = fmaxf(cnt1[gn], 1.0f);
                v.x /= c; v.y /= c; v.z /= c; v.w /= c;
            } else {
                v = ((const float4*)(sum2 + gn * DE))[c4 - 24];
                float c = fmaxf(cnt2[gn], 1.0f);
                v.x /= c; v.y /= c; v.z /= c; v.w /= c;
            }
        }
        *(float4*)(sIn + n * SIN_N_STRIDE + c4 * 4) = v;
    }
    __syncthreads();

    const int th = tid & 15;
    const int te = tid >> 4;

    // ---- Layer 1: [64n x 128] @ [128 x 64h] ----
    float acc[4][4];
    {
        const float4 b = *(const float4*)(sb1 + th * 4);
        #pragma unroll
        for (int i = 0; i < 4; i++) {
            acc[i][0] = b.x; acc[i][1] = b.y; acc[i][2] = b.z; acc[i][3] = b.w;
        }
    }
    const float* inRow = sIn + (te * 4) * SIN_N_STRIDE;
    for (int k = 0; k < DIN_N; k += 4) {
        float4 av4[4];
        #pragma unroll
        for (int i = 0; i < 4; i++)
            av4[i] = *(const float4*)(inRow + i * SIN_N_STRIDE + k);
        const float* a = (const float*)av4;
        #pragma unroll
        for (int kk = 0; kk < 4; kk++) {
            float4 w = *(const float4*)(sW1 + (k + kk) * DH + th * 4);
            #pragma unroll
            for (int i = 0; i < 4; i++) {
                float xv = a[i * 4 + kk];
                acc[i][0] += xv * w.x;
                acc[i][1] += xv * w.y;
                acc[i][2] += xv * w.z;
                acc[i][3] += xv * w.w;
            }
        }
    }
    #pragma unroll
    for (int i = 0; i < 4; i++) {
        float4 h;
        h.x = fmaxf(acc[i][0], 0.f);
        h.y = fmaxf(acc[i][1], 0.f);
        h.z = fmaxf(acc[i][2], 0.f);
        h.w = fmaxf(acc[i][3], 0.f);
        *(float4*)(sH + (te * 4 + i) * SH_STRIDE + th * 4) = h;
    }
    __syncthreads();

    // ---- Layer 2: [64n x 64h] @ [64h x 64o] ----
    float acc2[4][4];
    {
        const float4 b = *(const float4*)(sb2 + th * 4);
        #pragma unroll
        for (int i = 0; i < 4; i++) {
            acc2[i][0] = b.x; acc2[i][1] = b.y; acc2[i][2] = b.z; acc2[i][3] = b.w;
        }
    }
    const float* hRow = sH + (te * 4) * SH_STRIDE;
    for (int k = 0; k < DH; k += 4) {
        float4 av4[4];
        #pragma unroll
        for (int i = 0; i < 4; i++)
            av4[i] = *(const float4*)(hRow + i * SH_STRIDE + k);
        const float* a = (const float*)av4;
        #pragma unroll
        for (int kk = 0; kk < 4; kk++) {
            float4 w = *(const float4*)(sW2 + (k + kk) * DN + th * 4);
            #pragma unroll
            for (int i = 0; i < 4; i++) {
                float xv = a[i * 4 + kk];
                acc2[i][0] += xv * w.x;
                acc2[i][1] += xv * w.y;
                acc2[i][2] += xv * w.z;
                acc2[i][3] += xv * w.w;
            }
        }
    }
    #pragma unroll
    for (int i = 0; i < 4; i++) {
        int gn = n0 + te * 4 + i;
        if (gn < N_NODES) {
            float4 o;
            o.x = acc2[i][0]; o.y = acc2[i][1]; o.z = acc2[i][2]; o.w = acc2[i][3];
            *(float4*)(out + gn * DN + th * 4) = o;
        }
    }
}

#define EDGE_SMEM ((DIN_E*DH + DH*DE + DH + DE + TE*SIN_E_STRIDE + TE*SH_STRIDE + 2*TE) * 4)
#define NODE_SMEM ((DIN_N*DH + DH*DN + DH + DN + TN*SIN_N_STRIDE + TN*SH_STRIDE) * 4)

extern "C" void kernel_launch(void* const* d_in, const int* in_sizes, int n_in,
                              void* d_out, int out_size) {
    const float* x_a  = (const float*)d_in[0];
    const float* x_b  = (const float*)d_in[1];
    const int*   ei_aa = (const int*)d_in[2];
    const int*   ei_ab = (const int*)d_in[3];
    const int*   ei_bb = (const int*)d_in[4];
    const float* ea_aa = (const float*)d_in[5];
    const float* ea_ab = (const float*)d_in[6];
    const float* ea_bb = (const float*)d_in[7];
    const float* We1 = (const float*)d_in[8];
    const float* be1 = (const float*)d_in[9];
    const float* We2 = (const float*)d_in[10];
    const float* be2 = (const float*)d_in[11];
    const float* Wn1 = (const float*)d_in[12];
    const float* bn1 = (const float*)d_in[13];
    const float* Wn2 = (const float*)d_in[14];
    const float* bn2 = (const float*)d_in[15];

    float* out   = (float*)d_out;
    float* nx_a  = out;
    float* nx_b  = nx_a + (size_t)N_NODES * DN;
    float* ne_aa = nx_b + (size_t)N_NODES * DN;
    float* ne_ab = ne_aa + (size_t)E_EDGES * DE;
    float* ne_bb = ne_ab + (size_t)E_EDGES * DE;

    cudaFuncSetAttribute(edge_kernel, cudaFuncAttributeMaxDynamicSharedMemorySize, EDGE_SMEM);
    cudaFuncSetAttribute(node_kernel, cudaFuncAttributeMaxDynamicSharedMemorySize, NODE_SMEM);

    zero_kernel<<<1024, 256>>>();

    const int eb = E_EDGES / TE;  // 6250
    edge_kernel<<<eb, NT, EDGE_SMEM>>>(x_a, x_a, ei_aa, ea_aa,
        We1,                 be1,        We2,             be2,
        ne_aa, 0, -1);
    edge_kernel<<<eb, NT, EDGE_SMEM>>>(x_a, x_b, ei_ab, ea_ab,
        We1 + DIN_E * DH,    be1 + DH,   We2 + DH * DE,   be2 + DE,
        ne_ab, 1, 2);
    edge_kernel<<<eb, NT, EDGE_SMEM>>>(x_b, x_b, ei_bb, ea_bb,
        We1 + 2 * DIN_E * DH, be1 + 2 * DH, We2 + 2 * DH * DE, be2 + 2 * DE,
        ne_bb, 3, -1);

    const int nb = (N_NODES + TN - 1) / TN;  // 1563
    node_kernel<<<nb, NT, NODE_SMEM>>>(x_a, 0, 1,
        Wn1,               bn1,      Wn2,           bn2,      nx_a);
    node_kernel<<<nb, NT, NODE_SMEM>>>(x_b, 2, 3,
        Wn1 + DIN_N * DH,  bn1 + DH, Wn2 + DH * DN, bn2 + DN, nx_b);
}

// round 2
// speedup vs baseline: 1.4630x; 1.4630x over previous
#include <cuda_runtime.h>

#define N_NODES 100000
#define E_EDGES 400000
#define DN 64
#define DE 32
#define DH 64
#define DIN_E 160
#define DIN_N 128
#define TE 64
#define TN 64
#define NT 256
#define EB (E_EDGES / TE)               // 6250 (exact)
#define NB ((N_NODES + TN - 1) / TN)    // 1563
#define BSTR 68                          // 64 + 4 pad (bank skew)
#define NSTR 132                         // 128 + 4 pad

// Scratch for segment sums/counts (no cudaMalloc allowed).
// slots: 0 = a<-aa(row), 1 = a<-ab(row), 2 = b<-ab(col), 3 = b<-bb(row)
__device__ float g_sum[4][N_NODES * DE];
__device__ float g_cnt[4][N_NODES];

__global__ void zero_kernel() {
    int idx = blockIdx.x * blockDim.x + threadIdx.x;
    int stride = gridDim.x * blockDim.x;
    float* s = &g_sum[0][0];
    for (int i = idx; i < 4 * N_NODES * DE; i += stride) s[i] = 0.0f;
    float* c = &g_cnt[0][0];
    for (int i = idx; i < 4 * N_NODES; i += stride) c[i] = 0.0f;
}

// Accumulate acc[4e][4h] += buf[4 rows x KW] @ W[KW x 64h], W streamed via LDG.
template <int KW, int STR>
__device__ __forceinline__ void accum_l1(
    const float* buf, const float* __restrict__ W, int te, int th,
    float acc[4][4])
{
    const float* row = buf + (te * 4) * STR;
    #pragma unroll 4
    for (int k = 0; k < KW; k += 4) {
        float4 a0 = *(const float4*)(row + 0 * STR + k);
        float4 a1 = *(const float4*)(row + 1 * STR + k);
        float4 a2 = *(const float4*)(row + 2 * STR + k);
        float4 a3 = *(const float4*)(row + 3 * STR + k);
        const float* a[4] = {(const float*)&a0, (const float*)&a1,
                             (const float*)&a2, (const float*)&a3};
        #pragma unroll
        for (int kk = 0; kk < 4; kk++) {
            float4 w = __ldg((const float4*)(W + (k + kk) * DH) + th);
            #pragma unroll
            for (int i = 0; i < 4; i++) {
                float x = a[i][kk];
                acc[i][0] += x * w.x;
                acc[i][1] += x * w.y;
                acc[i][2] += x * w.z;
                acc[i][3] += x * w.w;
            }
        }
    }
}

// ---------------------------------------------------------------------------
// Edge kernel (all 3 types merged): per block, 64 edges.
// Phased gather (src64 | dst64 | ea32) through one 64x68 buffer; the same
// buffer is reused for the hidden activations. W1 via LDG (L1-resident).
// ---------------------------------------------------------------------------
__global__ void __launch_bounds__(NT, 4) edge_all(
    const float* __restrict__ x_a, const float* __restrict__ x_b,
    const int* __restrict__ ei_aa, const int* __restrict__ ei_ab,
    const int* __restrict__ ei_bb,
    const float* __restrict__ ea_aa, const float* __restrict__ ea_ab,
    const float* __restrict__ ea_bb,
    const float* __restrict__ We1, const float* __restrict__ be1,
    const float* __restrict__ We2, const float* __restrict__ be2,
    float* __restrict__ ne_base)
{
    __shared__ float buf[TE * BSTR];   // 17.4 KB, input chunks then hidden
    __shared__ float sW2[DH * DE];     // 8 KB
    __shared__ int sIdxR[TE];
    __shared__ int sIdxC[TE];

    const int tid = threadIdx.x;
    const int type = blockIdx.x / EB;
    const int eblk = blockIdx.x - type * EB;
    const int e0 = eblk * TE;

    const float* xsrc = (type == 2) ? x_b : x_a;
    const float* xdst = (type == 0) ? x_a : x_b;
    const int* ei = (type == 0) ? ei_aa : (type == 1) ? ei_ab : ei_bb;
    const float* ea = (type == 0) ? ea_aa : (type == 1) ? ea_ab : ea_bb;
    const float* W1 = We1 + type * DIN_E * DH;
    const float* b1 = be1 + type * DH;
    const float* W2 = We2 + type * DH * DE;
    const float* b2 = be2 + type * DE;
    float* ne = ne_base + (size_t)type * E_EDGES * DE;
    const int slot_row = (type == 0) ? 0 : (type == 1) ? 1 : 3;
    const bool has_col = (type == 1);

    // Stage W2 + edge indices
    for (int i = tid; i < DH * DE / 4; i += NT)
        ((float4*)sW2)[i] = ((const float4*)W2)[i];
    if (tid < TE) sIdxR[tid] = ei[e0 + tid];
    else if (tid < 2 * TE) sIdxC[tid - TE] = ei[E_EDGES + e0 + tid - TE];
    __syncthreads();

    const int th = tid & 15;
    const int te = tid >> 4;

    float acc[4][4];
    {
        float4 bv = __ldg((const float4*)b1 + th);
        #pragma unroll
        for (int i = 0; i < 4; i++) {
            acc[i][0] = bv.x; acc[i][1] = bv.y; acc[i][2] = bv.z; acc[i][3] = bv.w;
        }
    }

    // ---- phase 0: src features (cols 0..63) ----
    for (int it = tid; it < TE * 16; it += NT) {
        int e = it >> 4, c = it & 15;
        *(float4*)(buf + e * BSTR + c * 4) =
            __ldg((const float4*)(xsrc + (size_t)sIdxR[e] * DN) + c);
    }
    __syncthreads();
    accum_l1<64, BSTR>(buf, W1, te, th, acc);
    __syncthreads();

    // ---- phase 1: dst features (cols 64..127) ----
    for (int it = tid; it < TE * 16; it += NT) {
        int e = it >> 4, c = it & 15;
        *(float4*)(buf + e * BSTR + c * 4) =
            __ldg((const float4*)(xdst + (size_t)sIdxC[e] * DN) + c);
    }
    __syncthreads();
    accum_l1<64, BSTR>(buf, W1 + 64 * DH, te, th, acc);
    __syncthreads();

    // ---- phase 2: edge attrs (cols 128..159) ----
    for (int it = tid; it < TE * 8; it += NT) {
        int e = it >> 3, c = it & 7;
        *(float4*)(buf + e * BSTR + c * 4) =
            __ldg((const float4*)(ea + (size_t)(e0 + e) * DE) + c);
    }
    __syncthreads();
    accum_l1<32, BSTR>(buf, W1 + 128 * DH, te, th, acc);
    __syncthreads();

    // ReLU -> reuse buf as hidden [64e x 64h]
    #pragma unroll
    for (int i = 0; i < 4; i++) {
        float4 h;
        h.x = fmaxf(acc[i][0], 0.f);
        h.y = fmaxf(acc[i][1], 0.f);
        h.z = fmaxf(acc[i][2], 0.f);
        h.w = fmaxf(acc[i][3], 0.f);
        *(float4*)(buf + (te * 4 + i) * BSTR + th * 4) = h;
    }
    __syncthreads();

    // ---- Layer 2: [64e x 64h] @ [64h x 32o] ----
    float acc2[4][2];
    {
        float2 b2v = __ldg((const float2*)b2 + th);
        #pragma unroll
        for (int i = 0; i < 4; i++) { acc2[i][0] = b2v.x; acc2[i][1] = b2v.y; }
    }
    const float* hRow = buf + (te * 4) * BSTR;
    #pragma unroll 4
    for (int k = 0; k < DH; k += 4) {
        float4 a0 = *(const float4*)(hRow + 0 * BSTR + k);
        float4 a1 = *(const float4*)(hRow + 1 * BSTR + k);
        float4 a2 = *(const float4*)(hRow + 2 * BSTR + k);
        float4 a3 = *(const float4*)(hRow + 3 * BSTR + k);
        const float* a[4] = {(const float*)&a0, (const float*)&a1,
                             (const float*)&a2, (const float*)&a3};
        #pragma unroll
        for (int kk = 0; kk < 4; kk++) {
            float2 w = *(const float2*)(sW2 + (k + kk) * DE + th * 2);
            #pragma unroll
            for (int i = 0; i < 4; i++) {
                float x = a[i][kk];
                acc2[i][0] += x * w.x;
                acc2[i][1] += x * w.y;
            }
        }
    }

    // ---- Write ne + scatter atomics ----
    float* sum_row = g_sum[slot_row];
    float* cnt_row = g_cnt[slot_row];
    float* sum_col = has_col ? g_sum[2] : nullptr;
    float* cnt_col = has_col ? g_cnt[2] : nullptr;
    #pragma unroll
    for (int i = 0; i < 4; i++) {
        int e = te * 4 + i;
        int ge = e0 + e;
        float vx = acc2[i][0], vy = acc2[i][1];
        float2 v; v.x = vx; v.y = vy;
        *(float2*)(ne + (size_t)ge * DE + th * 2) = v;
        int r = sIdxR[e];
        atomicAdd(sum_row + r * DE + th * 2, vx);
        atomicAdd(sum_row + r * DE + th * 2 + 1, vy);
        if (has_col) {
            int c = sIdxC[e];
            atomicAdd(sum_col + c * DE + th * 2, vx);
            atomicAdd(sum_col + c * DE + th * 2 + 1, vy);
        }
        if (th == 0) {
            atomicAdd(cnt_row + r, 1.0f);
            if (has_col) atomicAdd(cnt_col + sIdxC[e], 1.0f);
        }
    }
}

// ---------------------------------------------------------------------------
// Node kernel (both types merged): per block, 64 nodes.
// Input [x(64) | mean1(32) | mean2(32)] staged in one 64x132 buffer,
// reused for hidden. W1/W2 via LDG.
// ---------------------------------------------------------------------------
__global__ void __launch_bounds__(NT, 4) node_all(
    const float* __restrict__ x_a, const float* __restrict__ x_b,
    const float* __restrict__ Wn1, const float* __restrict__ bn1,
    const float* __restrict__ Wn2, const float* __restrict__ bn2,
    float* __restrict__ out)
{
    __shared__ float buf[TN * NSTR];   // 33.8 KB

    const int tid = threadIdx.x;
    const int type = blockIdx.x / NB;
    const int nblk = blockIdx.x - type * NB;
    const int n0 = nblk * TN;

    const float* x = type ? x_b : x_a;
    const float* sum1 = g_sum[type ? 2 : 0];
    const float* cnt1 = g_cnt[type ? 2 : 0];
    const float* sum2 = g_sum[type ? 3 : 1];
    const float* cnt2 = g_cnt[type ? 3 : 1];
    const float* W1 = Wn1 + type * DIN_N * DH;
    const float* b1 = bn1 + type * DH;
    const float* W2 = Wn2 + type * DH * DN;
    const float* b2 = bn2 + type * DN;
    float* o = out + (size_t)type * N_NODES * DN;

    // Gather inputs: 32 float4 chunks per node
    for (int it = tid; it < TN * 32; it += NT) {
        int n = it >> 5, c4 = it & 31;
        int gn = n0 + n;
        float4 v = make_float4(0.f, 0.f, 0.f, 0.f);
        if (gn < N_NODES) {
            if (c4 < 16) {
                v = __ldg((const float4*)(x + (size_t)gn * DN) + c4);
            } else if (c4 < 24) {
                v = *((const float4*)(sum1 + (size_t)gn * DE) + (c4 - 16));
                float rc = 1.0f / fmaxf(cnt1[gn], 1.0f);
                v.x *= rc; v.y *= rc; v.z *= rc; v.w *= rc;
            } else {
                v = *((const float4*)(sum2 + (size_t)gn * DE) + (c4 - 24));
                float rc = 1.0f / fmaxf(cnt2[gn], 1.0f);
                v.x *= rc; v.y *= rc; v.z *= rc; v.w *= rc;
            }
        }
        *(float4*)(buf + n * NSTR + c4 * 4) = v;
    }
    __syncthreads();

    const int th = tid & 15;
    const int te = tid >> 4;

    // ---- Layer 1: [64n x 128] @ [128 x 64h] ----
    float acc[4][4];
    {
        float4 bv = __ldg((const float4*)b1 + th);
        #pragma unroll
        for (int i = 0; i < 4; i++) {
            acc[i][0] = bv.x; acc[i][1] = bv.y; acc[i][2] = bv.z; acc[i][3] = bv.w;
        }
    }
    accum_l1<128, NSTR>(buf, W1, te, th, acc);
    __syncthreads();

    // ReLU -> reuse buf as hidden [64n x 64h] (stride BSTR)
    #pragma unroll
    for (int i = 0; i < 4; i++) {
        float4 h;
        h.x = fmaxf(acc[i][0], 0.f);
        h.y = fmaxf(acc[i][1], 0.f);
        h.z = fmaxf(acc[i][2], 0.f);
        h.w = fmaxf(acc[i][3], 0.f);
        *(float4*)(buf + (te * 4 + i) * BSTR + th * 4) = h;
    }
    __syncthreads();

    // ---- Layer 2: [64n x 64h] @ [64h x 64o], W2 via LDG ----
    float acc2[4][4];
    {
        float4 bv = __ldg((const float4*)b2 + th);
        #pragma unroll
        for (int i = 0; i < 4; i++) {
            acc2[i][0] = bv.x; acc2[i][1] = bv.y; acc2[i][2] = bv.z; acc2[i][3] = bv.w;
        }
    }
    const float* hRow = buf + (te * 4) * BSTR;
    #pragma unroll 4
    for (int k = 0; k < DH; k += 4) {
        float4 a0 = *(const float4*)(hRow + 0 * BSTR + k);
        float4 a1 = *(const float4*)(hRow + 1 * BSTR + k);
        float4 a2 = *(const float4*)(hRow + 2 * BSTR + k);
        float4 a3 = *(const float4*)(hRow + 3 * BSTR + k);
        const float* a[4] = {(const float*)&a0, (const float*)&a1,
                             (const float*)&a2, (const float*)&a3};
        #pragma unroll
        for (int kk = 0; kk < 4; kk++) {
            float4 w = __ldg((const float4*)(W2 + (k + kk) * DN) + th);
            #pragma unroll
            for (int i = 0; i < 4; i++) {
                float xv = a[i][kk];
                acc2[i][0] += xv * w.x;
                acc2[i][1] += xv * w.y;
                acc2[i][2] += xv * w.z;
                acc2[i][3] += xv * w.w;
            }
        }
    }
    #pragma unroll
    for (int i = 0; i < 4; i++) {
        int gn = n0 + te * 4 + i;
        if (gn < N_NODES) {
            float4 ov;
            ov.x = acc2[i][0]; ov.y = acc2[i][1]; ov.z = acc2[i][2]; ov.w = acc2[i][3];
            *(float4*)(o + (size_t)gn * DN + th * 4) = ov;
        }
    }
}

extern "C" void kernel_launch(void* const* d_in, const int* in_sizes, int n_in,
                              void* d_out, int out_size) {
    const float* x_a  = (const float*)d_in[0];
    const float* x_b  = (const float*)d_in[1];
    const int*   ei_aa = (const int*)d_in[2];
    const int*   ei_ab = (const int*)d_in[3];
    const int*   ei_bb = (const int*)d_in[4];
    const float* ea_aa = (const float*)d_in[5];
    const float* ea_ab = (const float*)d_in[6];
    const float* ea_bb = (const float*)d_in[7];
    const float* We1 = (const float*)d_in[8];
    const float* be1 = (const float*)d_in[9];
    const float* We2 = (const float*)d_in[10];
    const float* be2 = (const float*)d_in[11];
    const float* Wn1 = (const float*)d_in[12];
    const float* bn1 = (const float*)d_in[13];
    const float* Wn2 = (const float*)d_in[14];
    const float* bn2 = (const float*)d_in[15];

    float* out   = (float*)d_out;
    float* nx_a  = out;
    float* ne_base = out + 2 * (size_t)N_NODES * DN;   // ne_aa, ne_ab, ne_bb

    zero_kernel<<<1024, 256>>>();

    edge_all<<<3 * EB, NT>>>(x_a, x_b, ei_aa, ei_ab, ei_bb,
                             ea_aa, ea_ab, ea_bb,
                             We1, be1, We2, be2, ne_base);

    node_all<<<2 * NB, NT>>>(x_a, x_b, Wn1, bn1, Wn2, bn2, nx_a);
}

// round 3
// speedup vs baseline: 1.5228x; 1.0409x over previous
#include <cuda_runtime.h>

#define N_NODES 100000
#define E_EDGES 400000
#define DN 64
#define DE 32
#define DH 64
#define DIN_E 160
#define DIN_N 128
#define TE 64
#define TN 64
#define NT 256
#define EB (E_EDGES / TE)               // 6250 (exact)
#define NB ((N_NODES + TN - 1) / TN)    // 1563
#define BSTR 68                          // 64 + 4 pad (bank skew)
#define NSTR 132                         // 128 + 4 pad

typedef unsigned long long u64;

// Scratch for segment sums/counts (no cudaMalloc allowed).
// slots: 0 = a<-aa(row), 1 = a<-ab(row), 2 = b<-ab(col), 3 = b<-bb(row)
__device__ float g_sum[4][N_NODES * DE];
__device__ float g_cnt[4][N_NODES];

__global__ void zero_kernel() {
    int idx = blockIdx.x * blockDim.x + threadIdx.x;
    int stride = gridDim.x * blockDim.x;
    float* s = &g_sum[0][0];
    for (int i = idx; i < 4 * N_NODES * DE; i += stride) s[i] = 0.0f;
    float* c = &g_cnt[0][0];
    for (int i = idx; i < 4 * N_NODES; i += stride) c[i] = 0.0f;
}

// ---- packed fp32x2 helpers (sm_103a) ----
__device__ __forceinline__ u64 pack_dup(float x) {
    u64 r;
    asm("mov.b64 %0, {%1, %1};" : "=l"(r) : "r"(__float_as_uint(x)));
    return r;
}
__device__ __forceinline__ u64 pack_pair(float x, float y) {
    u64 r;
    asm("mov.b64 %0, {%1, %2};" : "=l"(r) : "r"(__float_as_uint(x)), "r"(__float_as_uint(y)));
    return r;
}
__device__ __forceinline__ float2 unpack(u64 v) {
    float2 f;
    asm("mov.b64 {%0, %1}, %2;" : "=f"(f.x), "=f"(f.y) : "l"(v));
    return f;
}
__device__ __forceinline__ void fma2(u64& acc, u64 a, u64 b) {
    asm("fma.rn.f32x2 %0, %1, %2, %0;" : "+l"(acc) : "l"(a), "l"(b));
}

// Accumulate acc[4e][2 h-pairs] += buf[4 rows x KW] @ W[KW x 64h].
// W streamed via LDG.128 (pre-paired for f32x2).
template <int KW, int STR>
__device__ __forceinline__ void accum_l1(
    const float* buf, const float* __restrict__ W, int te, int th,
    u64 acc[4][2])
{
    const float* row = buf + (te * 4) * STR;
    #pragma unroll 4
    for (int k = 0; k < KW; k += 4) {
        float4 a0 = *(const float4*)(row + 0 * STR + k);
        float4 a1 = *(const float4*)(row + 1 * STR + k);
        float4 a2 = *(const float4*)(row + 2 * STR + k);
        float4 a3 = *(const float4*)(row + 3 * STR + k);
        const float* a[4] = {(const float*)&a0, (const float*)&a1,
                             (const float*)&a2, (const float*)&a3};
        #pragma unroll
        for (int kk = 0; kk < 4; kk++) {
            ulonglong2 wp = *((const ulonglong2*)(W + (k + kk) * DH) + th);
            #pragma unroll
            for (int i = 0; i < 4; i++) {
                u64 xx = pack_dup(a[i][kk]);
                fma2(acc[i][0], xx, wp.x);
                fma2(acc[i][1], xx, wp.y);
            }
        }
    }
}

// ---------------------------------------------------------------------------
// Edge kernel (all 3 types merged): per block, 64 edges.
// Phased gather (src64 | dst64 | ea32) through one 64x68 buffer; the same
// buffer is reused for the hidden activations. W1 via LDG (L1-resident).
// ---------------------------------------------------------------------------
__global__ void __launch_bounds__(NT, 4) edge_all(
    const float* __restrict__ x_a, const float* __restrict__ x_b,
    const int* __restrict__ ei_aa, const int* __restrict__ ei_ab,
    const int* __restrict__ ei_bb,
    const float* __restrict__ ea_aa, const float* __restrict__ ea_ab,
    const float* __restrict__ ea_bb,
    const float* __restrict__ We1, const float* __restrict__ be1,
    const float* __restrict__ We2, const float* __restrict__ be2,
    float* __restrict__ ne_base)
{
    __shared__ float buf[TE * BSTR];   // 17.4 KB, input chunks then hidden
    __shared__ float sW2[DH * DE];     // 8 KB
    __shared__ int sIdxR[TE];
    __shared__ int sIdxC[TE];

    const int tid = threadIdx.x;
    const int type = blockIdx.x / EB;
    const int eblk = blockIdx.x - type * EB;
    const int e0 = eblk * TE;

    const float* xsrc = (type == 2) ? x_b : x_a;
    const float* xdst = (type == 0) ? x_a : x_b;
    const int* ei = (type == 0) ? ei_aa : (type == 1) ? ei_ab : ei_bb;
    const float* ea = (type == 0) ? ea_aa : (type == 1) ? ea_ab : ea_bb;
    const float* W1 = We1 + type * DIN_E * DH;
    const float* b1 = be1 + type * DH;
    const float* W2 = We2 + type * DH * DE;
    const float* b2 = be2 + type * DE;
    float* ne = ne_base + (size_t)type * E_EDGES * DE;
    const int slot_row = (type == 0) ? 0 : (type == 1) ? 1 : 3;
    const bool has_col = (type == 1);

    // Stage W2 + edge indices
    for (int i = tid; i < DH * DE / 4; i += NT)
        ((float4*)sW2)[i] = ((const float4*)W2)[i];
    if (tid < TE) sIdxR[tid] = ei[e0 + tid];
    else if (tid < 2 * TE) sIdxC[tid - TE] = ei[E_EDGES + e0 + tid - TE];
    __syncthreads();

    const int th = tid & 15;
    const int te = tid >> 4;

    u64 acc[4][2];
    {
        float4 bv = __ldg((const float4*)b1 + th);
        u64 p0 = pack_pair(bv.x, bv.y);
        u64 p1 = pack_pair(bv.z, bv.w);
        #pragma unroll
        for (int i = 0; i < 4; i++) { acc[i][0] = p0; acc[i][1] = p1; }
    }

    // ---- phase 0: src features (cols 0..63) ----
    for (int it = tid; it < TE * 16; it += NT) {
        int e = it >> 4, c = it & 15;
        *(float4*)(buf + e * BSTR + c * 4) =
            __ldg((const float4*)(xsrc + (size_t)sIdxR[e] * DN) + c);
    }
    __syncthreads();
    accum_l1<64, BSTR>(buf, W1, te, th, acc);
    __syncthreads();

    // ---- phase 1: dst features (cols 64..127) ----
    for (int it = tid; it < TE * 16; it += NT) {
        int e = it >> 4, c = it & 15;
        *(float4*)(buf + e * BSTR + c * 4) =
            __ldg((const float4*)(xdst + (size_t)sIdxC[e] * DN) + c);
    }
    __syncthreads();
    accum_l1<64, BSTR>(buf, W1 + 64 * DH, te, th, acc);
    __syncthreads();

    // ---- phase 2: edge attrs (cols 128..159) ----
    for (int it = tid; it < TE * 8; it += NT) {
        int e = it >> 3, c = it & 7;
        *(float4*)(buf + e * BSTR + c * 4) =
            __ldg((const float4*)(ea + (size_t)(e0 + e) * DE) + c);
    }
    __syncthreads();
    accum_l1<32, BSTR>(buf, W1 + 128 * DH, te, th, acc);
    __syncthreads();

    // ReLU -> reuse buf as hidden [64e x 64h]
    #pragma unroll
    for (int i = 0; i < 4; i++) {
        float2 h0 = unpack(acc[i][0]);
        float2 h1 = unpack(acc[i][1]);
        float4 h;
        h.x = fmaxf(h0.x, 0.f);
        h.y = fmaxf(h0.y, 0.f);
        h.z = fmaxf(h1.x, 0.f);
        h.w = fmaxf(h1.y, 0.f);
        *(float4*)(buf + (te * 4 + i) * BSTR + th * 4) = h;
    }
    __syncthreads();

    // ---- Layer 2: [64e x 64h] @ [64h x 32o] ----
    u64 acc2[4];
    {
        float2 b2v = __ldg((const float2*)b2 + th);
        u64 p = pack_pair(b2v.x, b2v.y);
        #pragma unroll
        for (int i = 0; i < 4; i++) acc2[i] = p;
    }
    const float* hRow = buf + (te * 4) * BSTR;
    #pragma unroll 4
    for (int k = 0; k < DH; k += 4) {
        float4 a0 = *(const float4*)(hRow + 0 * BSTR + k);
        float4 a1 = *(const float4*)(hRow + 1 * BSTR + k);
        float4 a2 = *(const float4*)(hRow + 2 * BSTR + k);
        float4 a3 = *(const float4*)(hRow + 3 * BSTR + k);
        const float* a[4] = {(const float*)&a0, (const float*)&a1,
                             (const float*)&a2, (const float*)&a3};
        #pragma unroll
        for (int kk = 0; kk < 4; kk++) {
            u64 w = *((const u64*)(sW2 + (k + kk) * DE) + th);
            #pragma unroll
            for (int i = 0; i < 4; i++)
                fma2(acc2[i], pack_dup(a[i][kk]), w);
        }
    }

    // ---- Write ne + scatter atomics ----
    float* sum_row = g_sum[slot_row];
    float* cnt_row = g_cnt[slot_row];
    float* sum_col = has_col ? g_sum[2] : nullptr;
    float* cnt_col = has_col ? g_cnt[2] : nullptr;
    #pragma unroll
    for (int i = 0; i < 4; i++) {
        int e = te * 4 + i;
        int ge = e0 + e;
        float2 v = unpack(acc2[i]);
        *(float2*)(ne + (size_t)ge * DE + th * 2) = v;
        int r = sIdxR[e];
        atomicAdd(sum_row + r * DE + th * 2, v.x);
        atomicAdd(sum_row + r * DE + th * 2 + 1, v.y);
        if (has_col) {
            int c = sIdxC[e];
            atomicAdd(sum_col + c * DE + th * 2, v.x);
            atomicAdd(sum_col + c * DE + th * 2 + 1, v.y);
        }
        if (th == 0) {
            atomicAdd(cnt_row + r, 1.0f);
            if (has_col) atomicAdd(cnt_col + sIdxC[e], 1.0f);
        }
    }
}

// ---------------------------------------------------------------------------
// Node kernel (both types merged): per block, 64 nodes.
// Input [x(64) | mean1(32) | mean2(32)] staged in one 64x132 buffer,
// reused for hidden. W1/W2 via LDG.
// ---------------------------------------------------------------------------
__global__ void __launch_bounds__(NT, 4) node_all(
    const float* __restrict__ x_a, const float* __restrict__ x_b,
    const float* __restrict__ Wn1, const float* __restrict__ bn1,
    const float* __restrict__ Wn2, const float* __restrict__ bn2,
    float* __restrict__ out)
{
    __shared__ float buf[TN * NSTR];   // 33.8 KB

    const int tid = threadIdx.x;
    const int type = blockIdx.x / NB;
    const int nblk = blockIdx.x - type * NB;
    const int n0 = nblk * TN;

    const float* x = type ? x_b : x_a;
    const float* sum1 = g_sum[type ? 2 : 0];
    const float* cnt1 = g_cnt[type ? 2 : 0];
    const float* sum2 = g_sum[type ? 3 : 1];
    const float* cnt2 = g_cnt[type ? 3 : 1];
    const float* W1 = Wn1 + type * DIN_N * DH;
    const float* b1 = bn1 + type * DH;
    const float* W2 = Wn2 + type * DH * DN;
    const float* b2 = bn2 + type * DN;
    float* o = out + (size_t)type * N_NODES * DN;

    // Gather inputs: 32 float4 chunks per node
    for (int it = tid; it < TN * 32; it += NT) {
        int n = it >> 5, c4 = it & 31;
        int gn = n0 + n;
        float4 v = make_float4(0.f, 0.f, 0.f, 0.f);
        if (gn < N_NODES) {
            if (c4 < 16) {
                v = __ldg((const float4*)(x + (size_t)gn * DN) + c4);
            } else if (c4 < 24) {
                v = *((const float4*)(sum1 + (size_t)gn * DE) + (c4 - 16));
                float rc = 1.0f / fmaxf(cnt1[gn], 1.0f);
                v.x *= rc; v.y *= rc; v.z *= rc; v.w *= rc;
            } else {
                v = *((const float4*)(sum2 + (size_t)gn * DE) + (c4 - 24));
                float rc = 1.0f / fmaxf(cnt2[gn], 1.0f);
                v.x *= rc; v.y *= rc; v.z *= rc; v.w *= rc;
            }
        }
        *(float4*)(buf + n * NSTR + c4 * 4) = v;
    }
    __syncthreads();

    const int th = tid & 15;
    const int te = tid >> 4;

    // ---- Layer 1: [64n x 128] @ [128 x 64h] ----
    u64 acc[4][2];
    {
        float4 bv = __ldg((const float4*)b1 + th);
        u64 p0 = pack_pair(bv.x, bv.y);
        u64 p1 = pack_pair(bv.z, bv.w);
        #pragma unroll
        for (int i = 0; i < 4; i++) { acc[i][0] = p0; acc[i][1] = p1; }
    }
    accum_l1<128, NSTR>(buf, W1, te, th, acc);
    __syncthreads();

    // ReLU -> reuse buf as hidden [64n x 64h] (stride BSTR)
    #pragma unroll
    for (int i = 0; i < 4; i++) {
        float2 h0 = unpack(acc[i][0]);
        float2 h1 = unpack(acc[i][1]);
        float4 h;
        h.x = fmaxf(h0.x, 0.f);
        h.y = fmaxf(h0.y, 0.f);
        h.z = fmaxf(h1.x, 0.f);
        h.w = fmaxf(h1.y, 0.f);
        *(float4*)(buf + (te * 4 + i) * BSTR + th * 4) = h;
    }
    __syncthreads();

    // ---- Layer 2: [64n x 64h] @ [64h x 64o], W2 via LDG ----
    u64 acc2[4][2];
    {
        float4 bv = __ldg((const float4*)b2 + th);
        u64 p0 = pack_pair(bv.x, bv.y);
        u64 p1 = pack_pair(bv.z, bv.w);
        #pragma unroll
        for (int i = 0; i < 4; i++) { acc2[i][0] = p0; acc2[i][1] = p1; }
    }
    accum_l1<64, BSTR>(buf, W2, te, th, acc2);

    #pragma unroll
    for (int i = 0; i < 4; i++) {
        int gn = n0 + te * 4 + i;
        if (gn < N_NODES) {
            float2 o0 = unpack(acc2[i][0]);
            float2 o1 = unpack(acc2[i][1]);
            float4 ov;
            ov.x = o0.x; ov.y = o0.y; ov.z = o1.x; ov.w = o1.y;
            *(float4*)(o + (size_t)gn * DN + th * 4) = ov;
        }
    }
}

extern "C" void kernel_launch(void* const* d_in, const int* in_sizes, int n_in,
                              void* d_out, int out_size) {
    const float* x_a  = (const float*)d_in[0];
    const float* x_b  = (const float*)d_in[1];
    const int*   ei_aa = (const int*)d_in[2];
    const int*   ei_ab = (const int*)d_in[3];
    const int*   ei_bb = (const int*)d_in[4];
    const float* ea_aa = (const float*)d_in[5];
    const float* ea_ab = (const float*)d_in[6];
    const float* ea_bb = (const float*)d_in[7];
    const float* We1 = (const float*)d_in[8];
    const float* be1 = (const float*)d_in[9];
    const float* We2 = (const float*)d_in[10];
    const float* be2 = (const float*)d_in[11];
    const float* Wn1 = (const float*)d_in[12];
    const float* bn1 = (const float*)d_in[13];
    const float* Wn2 = (const float*)d_in[14];
    const float* bn2 = (const float*)d_in[15];

    float* out   = (float*)d_out;
    float* nx_a  = out;
    float* ne_base = out + 2 * (size_t)N_NODES * DN;   // ne_aa, ne_ab, ne_bb

    zero_kernel<<<1024, 256>>>();

    edge_all<<<3 * EB, NT>>>(x_a, x_b, ei_aa, ei_ab, ei_bb,
                             ea_aa, ea_ab, ea_bb,
                             We1, be1, We2, be2, ne_base);

    node_all<<<2 * NB, NT>>>(x_a, x_b, Wn1, bn1, Wn2, bn2, nx_a);
}

// round 4
// speedup vs baseline: 2.2496x; 1.4773x over previous
#include <cuda_runtime.h>

#define N_NODES 100000
#define E_EDGES 400000
#define DN 64
#define DE 32
#define DH 64
#define DIN_E 160
#define DIN_N 128
#define TE 64
#define TN 64
#define NT 256
#define EB (E_EDGES / TE)               // 6250 (exact)
#define NB ((N_NODES + TN - 1) / TN)    // 1563
#define BSTR 68                          // 64 + 4 pad (bank skew)
#define NSTR 132                         // 128 + 4 pad

typedef unsigned long long u64;

// Scratch (no cudaMalloc allowed).
// slots: 0 = a<-aa(row), 1 = a<-ab(row), 2 = b<-ab(col), 3 = b<-bb(row)
__device__ float g_sum[4][N_NODES * DE];
__device__ float g_cnt[4][N_NODES];
// Precomputed per-node edge-layer1 partials.
// seg: 0=P0(xa,A0,+b) 1=Q0(xa,B0) 2=P1(xa,A1,+b) 3=Q1(xb,B1) 4=P2(xb,A2,+b) 5=Q2(xb,B2)
__device__ float g_PQ[6][N_NODES * DH];

__global__ void zero_kernel() {
    int idx = blockIdx.x * blockDim.x + threadIdx.x;
    int stride = gridDim.x * blockDim.x;
    float* s = &g_sum[0][0];
    for (int i = idx; i < 4 * N_NODES * DE; i += stride) s[i] = 0.0f;
    float* c = &g_cnt[0][0];
    for (int i = idx; i < 4 * N_NODES; i += stride) c[i] = 0.0f;
}

// ---- packed fp32x2 helpers (sm_103a) ----
__device__ __forceinline__ u64 pack_dup(float x) {
    u64 r;
    asm("mov.b64 %0, {%1, %1};" : "=l"(r) : "r"(__float_as_uint(x)));
    return r;
}
__device__ __forceinline__ u64 pack_pair(float x, float y) {
    u64 r;
    asm("mov.b64 %0, {%1, %2};" : "=l"(r) : "r"(__float_as_uint(x)), "r"(__float_as_uint(y)));
    return r;
}
__device__ __forceinline__ float2 unpack(u64 v) {
    float2 f;
    asm("mov.b64 {%0, %1}, %2;" : "=f"(f.x), "=f"(f.y) : "l"(v));
    return f;
}
__device__ __forceinline__ void fma2(u64& acc, u64 a, u64 b) {
    asm("fma.rn.f32x2 %0, %1, %2, %0;" : "+l"(acc) : "l"(a), "l"(b));
}

// Accumulate acc[4r][2 h-pairs] += buf[4 rows x KW] @ W[KW x 64].
// W streamed via LDG.128 (pre-paired for f32x2).
template <int KW, int STR>
__device__ __forceinline__ void accum_l1(
    const float* buf, const float* __restrict__ W, int te, int th,
    u64 acc[4][2])
{
    const float* row = buf + (te * 4) * STR;
    #pragma unroll 4
    for (int k = 0; k < KW; k += 4) {
        float4 a0 = *(const float4*)(row + 0 * STR + k);
        float4 a1 = *(const float4*)(row + 1 * STR + k);
        float4 a2 = *(const float4*)(row + 2 * STR + k);
        float4 a3 = *(const float4*)(row + 3 * STR + k);
        const float* a[4] = {(const float*)&a0, (const float*)&a1,
                             (const float*)&a2, (const float*)&a3};
        #pragma unroll
        for (int kk = 0; kk < 4; kk++) {
            ulonglong2 wp = *((const ulonglong2*)(W + (k + kk) * DH) + th);
            #pragma unroll
            for (int i = 0; i < 4; i++) {
                u64 xx = pack_dup(a[i][kk]);
                fma2(acc[i][0], xx, wp.x);
                fma2(acc[i][1], xx, wp.y);
            }
        }
    }
}

// ---------------------------------------------------------------------------
// Precompute kernel: 6 dense GEMMs  g_PQ[seg] = x @ Wblk (+bias for P segs).
// x: [100K x 64], Wblk: [64 x 64]. Per block: 64 rows.
// ---------------------------------------------------------------------------
__global__ void __launch_bounds__(NT, 4) pre_gemm(
    const float* __restrict__ x_a, const float* __restrict__ x_b,
    const float* __restrict__ We1, const float* __restrict__ be1)
{
    __shared__ float buf[TN * BSTR];

    const int tid = threadIdx.x;
    const int seg = blockIdx.x / NB;
    const int rblk = blockIdx.x - seg * NB;
    const int r0 = rblk * TN;

    const int type = seg >> 1;
    const int part = seg & 1;               // 0 = P (src block), 1 = Q (dst block)
    const float* x = (seg <= 2) ? x_a : x_b;
    const float* W = We1 + type * DIN_E * DH + part * 64 * DH;
    float* outp = g_PQ[seg];

    // Stage x tile [64 x 64]
    for (int it = tid; it < TN * 16; it += NT) {
        int n = it >> 4, c = it & 15;
        int gn = r0 + n; if (gn >= N_NODES) gn = N_NODES - 1;
        *(float4*)(buf + n * BSTR + c * 4) =
            __ldg((const float4*)(x + (size_t)gn * DN) + c);
    }
    __syncthreads();

    const int th = tid & 15;
    const int te = tid >> 4;

    u64 acc[4][2];
    if (part == 0) {
        float4 bv = __ldg((const float4*)(be1 + type * DH) + th);
        u64 p0 = pack_pair(bv.x, bv.y);
        u64 p1 = pack_pair(bv.z, bv.w);
        #pragma unroll
        for (int i = 0; i < 4; i++) { acc[i][0] = p0; acc[i][1] = p1; }
    } else {
        #pragma unroll
        for (int i = 0; i < 4; i++) { acc[i][0] = 0ull; acc[i][1] = 0ull; }
    }

    accum_l1<64, BSTR>(buf, W, te, th, acc);

    #pragma unroll
    for (int i = 0; i < 4; i++) {
        int gn = r0 + te * 4 + i;
        if (gn < N_NODES) {
            float2 o0 = unpack(acc[i][0]);
            float2 o1 = unpack(acc[i][1]);
            float4 ov; ov.x = o0.x; ov.y = o0.y; ov.z = o1.x; ov.w = o1.y;
            *(float4*)(outp + (size_t)gn * DH + th * 4) = ov;
        }
    }
}

// ---------------------------------------------------------------------------
// Edge kernel (all 3 types merged): per block, 64 edges.
// acc = ea_tile @ C  (C = W1 rows 128..159), then h = relu(acc + P[src] + Q[dst]),
// layer 2, write ne, scatter atomics.
// ---------------------------------------------------------------------------
__global__ void __launch_bounds__(NT, 4) edge_all(
    const int* __restrict__ ei_aa, const int* __restrict__ ei_ab,
    const int* __restrict__ ei_bb,
    const float* __restrict__ ea_aa, const float* __restrict__ ea_ab,
    const float* __restrict__ ea_bb,
    const float* __restrict__ We1,
    const float* __restrict__ We2, const float* __restrict__ be2,
    float* __restrict__ ne_base)
{
    __shared__ float buf[TE * BSTR];   // ea tile (cols 0..31) then hidden
    __shared__ float sW2[DH * DE];     // 8 KB
    __shared__ int sIdxR[TE];
    __shared__ int sIdxC[TE];

    const int tid = threadIdx.x;
    const int type = blockIdx.x / EB;
    const int eblk = blockIdx.x - type * EB;
    const int e0 = eblk * TE;

    const int* ei = (type == 0) ? ei_aa : (type == 1) ? ei_ab : ei_bb;
    const float* ea = (type == 0) ? ea_aa : (type == 1) ? ea_ab : ea_bb;
    const float* C  = We1 + type * DIN_E * DH + 128 * DH;   // [32 x 64]
    const float* W2 = We2 + type * DH * DE;
    const float* b2 = be2 + type * DE;
    const float* P = g_PQ[2 * type];
    const float* Q = g_PQ[2 * type + 1];
    float* ne = ne_base + (size_t)type * E_EDGES * DE;
    const int slot_row = (type == 0) ? 0 : (type == 1) ? 1 : 3;
    const bool has_col = (type == 1);

    // Stage W2 + edge indices + ea tile
    for (int i = tid; i < DH * DE / 4; i += NT)
        ((float4*)sW2)[i] = ((const float4*)W2)[i];
    if (tid < TE) sIdxR[tid] = ei[e0 + tid];
    else if (tid < 2 * TE) sIdxC[tid - TE] = ei[E_EDGES + e0 + tid - TE];
    for (int it = tid; it < TE * 8; it += NT) {
        int e = it >> 3, c = it & 7;
        *(float4*)(buf + e * BSTR + c * 4) =
            __ldg((const float4*)(ea + (size_t)(e0 + e) * DE) + c);
    }
    __syncthreads();

    const int th = tid & 15;
    const int te = tid >> 4;

    // acc = ea @ C
    u64 acc[4][2];
    #pragma unroll
    for (int i = 0; i < 4; i++) { acc[i][0] = 0ull; acc[i][1] = 0ull; }
    accum_l1<32, BSTR>(buf, C, te, th, acc);

    // h = relu(acc + P[src] + Q[dst])  (bias folded into P)
    float4 hv[4];
    #pragma unroll
    for (int i = 0; i < 4; i++) {
        int e = te * 4 + i;
        float4 p = __ldg((const float4*)(P + (size_t)sIdxR[e] * DH) + th);
        float4 q = __ldg((const float4*)(Q + (size_t)sIdxC[e] * DH) + th);
        float2 a0 = unpack(acc[i][0]);
        float2 a1 = unpack(acc[i][1]);
        hv[i].x = fmaxf(a0.x + p.x + q.x, 0.f);
        hv[i].y = fmaxf(a0.y + p.y + q.y, 0.f);
        hv[i].z = fmaxf(a1.x + p.z + q.z, 0.f);
        hv[i].w = fmaxf(a1.y + p.w + q.w, 0.f);
    }
    __syncthreads();   // all reads of ea tile done
    #pragma unroll
    for (int i = 0; i < 4; i++)
        *(float4*)(buf + (te * 4 + i) * BSTR + th * 4) = hv[i];
    __syncthreads();

    // ---- Layer 2: [64e x 64h] @ [64h x 32o] ----
    u64 acc2[4];
    {
        float2 b2v = __ldg((const float2*)b2 + th);
        u64 p = pack_pair(b2v.x, b2v.y);
        #pragma unroll
        for (int i = 0; i < 4; i++) acc2[i] = p;
    }
    const float* hRow = buf + (te * 4) * BSTR;
    #pragma unroll 4
    for (int k = 0; k < DH; k += 4) {
        float4 a0 = *(const float4*)(hRow + 0 * BSTR + k);
        float4 a1 = *(const float4*)(hRow + 1 * BSTR + k);
        float4 a2 = *(const float4*)(hRow + 2 * BSTR + k);
        float4 a3 = *(const float4*)(hRow + 3 * BSTR + k);
        const float* a[4] = {(const float*)&a0, (const float*)&a1,
                             (const float*)&a2, (const float*)&a3};
        #pragma unroll
        for (int kk = 0; kk < 4; kk++) {
            u64 w = *((const u64*)(sW2 + (k + kk) * DE) + th);
            #pragma unroll
            for (int i = 0; i < 4; i++)
                fma2(acc2[i], pack_dup(a[i][kk]), w);
        }
    }

    // ---- Write ne + scatter atomics ----
    float* sum_row = g_sum[slot_row];
    float* cnt_row = g_cnt[slot_row];
    float* sum_col = has_col ? g_sum[2] : nullptr;
    float* cnt_col = has_col ? g_cnt[2] : nullptr;
    #pragma unroll
    for (int i = 0; i < 4; i++) {
        int e = te * 4 + i;
        int ge = e0 + e;
        float2 v = unpack(acc2[i]);
        *(float2*)(ne + (size_t)ge * DE + th * 2) = v;
        int r = sIdxR[e];
        atomicAdd(sum_row + r * DE + th * 2, v.x);
        atomicAdd(sum_row + r * DE + th * 2 + 1, v.y);
        if (has_col) {
            int c = sIdxC[e];
            atomicAdd(sum_col + c * DE + th * 2, v.x);
            atomicAdd(sum_col + c * DE + th * 2 + 1, v.y);
        }
        if (th == 0) {
            atomicAdd(cnt_row + r, 1.0f);
            if (has_col) atomicAdd(cnt_col + sIdxC[e], 1.0f);
        }
    }
}

// ---------------------------------------------------------------------------
// Node kernel (both types merged): per block, 64 nodes.
// ---------------------------------------------------------------------------
__global__ void __launch_bounds__(NT, 4) node_all(
    const float* __restrict__ x_a, const float* __restrict__ x_b,
    const float* __restrict__ Wn1, const float* __restrict__ bn1,
    const float* __restrict__ Wn2, const float* __restrict__ bn2,
    float* __restrict__ out)
{
    __shared__ float buf[TN * NSTR];   // 33.8 KB

    const int tid = threadIdx.x;
    const int type = blockIdx.x / NB;
    const int nblk = blockIdx.x - type * NB;
    const int n0 = nblk * TN;

    const float* x = type ? x_b : x_a;
    const float* sum1 = g_sum[type ? 2 : 0];
    const float* cnt1 = g_cnt[type ? 2 : 0];
    const float* sum2 = g_sum[type ? 3 : 1];
    const float* cnt2 = g_cnt[type ? 3 : 1];
    const float* W1 = Wn1 + type * DIN_N * DH;
    const float* b1 = bn1 + type * DH;
    const float* W2 = Wn2 + type * DH * DN;
    const float* b2 = bn2 + type * DN;
    float* o = out + (size_t)type * N_NODES * DN;

    // Gather inputs: 32 float4 chunks per node
    for (int it = tid; it < TN * 32; it += NT) {
        int n = it >> 5, c4 = it & 31;
        int gn = n0 + n;
        float4 v = make_float4(0.f, 0.f, 0.f, 0.f);
        if (gn < N_NODES) {
            if (c4 < 16) {
                v = __ldg((const float4*)(x + (size_t)gn * DN) + c4);
            } else if (c4 < 24) {
                v = *((const float4*)(sum1 + (size_t)gn * DE) + (c4 - 16));
                float rc = 1.0f / fmaxf(cnt1[gn], 1.0f);
                v.x *= rc; v.y *= rc; v.z *= rc; v.w *= rc;
            } else {
                v = *((const float4*)(sum2 + (size_t)gn * DE) + (c4 - 24));
                float rc = 1.0f / fmaxf(cnt2[gn], 1.0f);
                v.x *= rc; v.y *= rc; v.z *= rc; v.w *= rc;
            }
        }
        *(float4*)(buf + n * NSTR + c4 * 4) = v;
    }
    __syncthreads();

    const int th = tid & 15;
    const int te = tid >> 4;

    // ---- Layer 1: [64n x 128] @ [128 x 64h] ----
    u64 acc[4][2];
    {
        float4 bv = __ldg((const float4*)b1 + th);
        u64 p0 = pack_pair(bv.x, bv.y);
        u64 p1 = pack_pair(bv.z, bv.w);
        #pragma unroll
        for (int i = 0; i < 4; i++) { acc[i][0] = p0; acc[i][1] = p1; }
    }
    accum_l1<128, NSTR>(buf, W1, te, th, acc);
    __syncthreads();

    // ReLU -> reuse buf as hidden [64n x 64h] (stride BSTR)
    #pragma unroll
    for (int i = 0; i < 4; i++) {
        float2 h0 = unpack(acc[i][0]);
        float2 h1 = unpack(acc[i][1]);
        float4 h;
        h.x = fmaxf(h0.x, 0.f);
        h.y = fmaxf(h0.y, 0.f);
        h.z = fmaxf(h1.x, 0.f);
        h.w = fmaxf(h1.y, 0.f);
        *(float4*)(buf + (te * 4 + i) * BSTR + th * 4) = h;
    }
    __syncthreads();

    // ---- Layer 2: [64n x 64h] @ [64h x 64o], W2 via LDG ----
    u64 acc2[4][2];
    {
        float4 bv = __ldg((const float4*)b2 + th);
        u64 p0 = pack_pair(bv.x, bv.y);
        u64 p1 = pack_pair(bv.z, bv.w);
        #pragma unroll
        for (int i = 0; i < 4; i++) { acc2[i][0] = p0; acc2[i][1] = p1; }
    }
    accum_l1<64, BSTR>(buf, W2, te, th, acc2);

    #pragma unroll
    for (int i = 0; i < 4; i++) {
        int gn = n0 + te * 4 + i;
        if (gn < N_NODES) {
            float2 o0 = unpack(acc2[i][0]);
            float2 o1 = unpack(acc2[i][1]);
            float4 ov;
            ov.x = o0.x; ov.y = o0.y; ov.z = o1.x; ov.w = o1.y;
            *(float4*)(o + (size_t)gn * DN + th * 4) = ov;
        }
    }
}

extern "C" void kernel_launch(void* const* d_in, const int* in_sizes, int n_in,
                              void* d_out, int out_size) {
    const float* x_a  = (const float*)d_in[0];
    const float* x_b  = (const float*)d_in[1];
    const int*   ei_aa = (const int*)d_in[2];
    const int*   ei_ab = (const int*)d_in[3];
    const int*   ei_bb = (const int*)d_in[4];
    const float* ea_aa = (const float*)d_in[5];
    const float* ea_ab = (const float*)d_in[6];
    const float* ea_bb = (const float*)d_in[7];
    const float* We1 = (const float*)d_in[8];
    const float* be1 = (const float*)d_in[9];
    const float* We2 = (const float*)d_in[10];
    const float* be2 = (const float*)d_in[11];
    const float* Wn1 = (const float*)d_in[12];
    const float* bn1 = (const float*)d_in[13];
    const float* Wn2 = (const float*)d_in[14];
    const float* bn2 = (const float*)d_in[15];

    float* out   = (float*)d_out;
    float* nx_a  = out;
    float* ne_base = out + 2 * (size_t)N_NODES * DN;   // ne_aa, ne_ab, ne_bb

    zero_kernel<<<1024, 256>>>();

    pre_gemm<<<6 * NB, NT>>>(x_a, x_b, We1, be1);

    edge_all<<<3 * EB, NT>>>(ei_aa, ei_ab, ei_bb,
                             ea_aa, ea_ab, ea_bb,
                             We1, We2, be2, ne_base);

    node_all<<<2 * NB, NT>>>(x_a, x_b, Wn1, bn1, Wn2, bn2, nx_a);
}